// round 16
// baseline (speedup 1.0000x reference)
#include <cuda_runtime.h>

#define H      768
#define DD     192
#define WIN    960
#define NCOMBO (8 * 17)
#define SEQ    2048
#define LN_EPS 1e-12f
#define TOK_PER_BLK 16

#define KC      64
#define KC4     16
#define NK_TOK  12          // 768/64
#define NK_DIN  3           // 192/64
#define NCT     24
#define SWP     33

#define NB_TOK   (NK_TOK * NCT)          // 288
#define NB_DIN   (NK_DIN * NCT)          // 72
#define NB_P     (NB_TOK + NB_DIN)       // 360 GEMM blocks
#define NB_COMBO 64
#define NB_WORK  (NB_P + NB_COMBO + NCOMBO)   // 560

// Scratch (no cudaMalloc allowed). All counters are MONOTONIC across graph
// replays (never reset): gating blocks derive their replay epoch from a
// ticket on g_started, and gate on cnt >= (epoch+1)*target. Stream-serialized
// launches make epochs exact.
__device__ float g_ptok[NK_TOK * 8 * H];
__device__ float g_pdin[NK_DIN * 16 * H];
__device__ float g_table[NCOMBO * H];
__device__ uint4 g_combo4[4096];
__device__ int   g_cnt_partial;   // += NB_P      per launch
__device__ int   g_cnt_combo;     // += NB_COMBO  per launch
__device__ int   g_cnt_table;     // += NCOMBO    per launch
__device__ int   g_started;       // += (NCOMBO + nb_gather) per launch

// ---------------------------------------------------------------------------
// Single mega-kernel. 256 threads, __launch_bounds__(256,4) caps regs at 64:
// 4 blocks/SM x 148 SMs = 592 resident slots >= 560 worker blocks, so all
// producers are resident in wave 1 and the gates cannot deadlock.
//   blocks [0,360)       : K-split GEMM partials
//   blocks [360,424)     : combo precompute (overlaps GEMM)
//   blocks [424,560)     : table rows     (gate: cnt_partial)
//   blocks [560,560+nbg) : gather          (gate: cnt_table, cnt_combo);
//                          threads 0..191 run the R15 prefetch-ring copy
//                          (fully unrolled -> no local-memory indexing).
// ---------------------------------------------------------------------------
__global__ __launch_bounds__(256, 4) void mega_kernel(
    const int*   __restrict__ ids32,
    const float* __restrict__ tok_emb,   // [8, 768]
    const float* __restrict__ din_emb,   // [16, 192]
    const float* __restrict__ W,         // [768, 960]
    const float* __restrict__ bias,
    const float* __restrict__ gamma,
    const float* __restrict__ beta,
    float*       __restrict__ out,
    int n_tokens,
    int nb_gather)
{
    __shared__ float smem_buf[7232];     // 28.9 KB
    const int tid = threadIdx.x;
    const int bid = blockIdx.x;

    if (bid < NB_P) {
        // ==================== GEMM partials ====================
        const int ch = tid & 31;
        const int kq = tid >> 5;
        const float4* W4 = reinterpret_cast<const float4*>(W);

        if (bid < NB_TOK) {
            const int kc = bid / NCT;
            const int ct = bid % NCT;

            float* sW   = smem_buf;
            float* sET  = smem_buf + 2112;
            float* sAcc = smem_buf + 2112 + 512;

            #pragma unroll
            for (int t = 0; t < 2; t++) {
                const int idx = t * 256 + tid;
                const int c   = idx / KC4;
                const int k4  = idx % KC4;
                const float4 w = __ldg(&W4[(size_t)(ct * 32 + c) * (WIN / 4) + kc * KC4 + k4]);
                float* dst = &sW[(k4 * 4) * SWP + c];
                dst[0 * SWP] = w.x; dst[1 * SWP] = w.y; dst[2 * SWP] = w.z; dst[3 * SWP] = w.w;
            }
            if (tid < 128) {
                const int row = tid >> 4;
                const int k4  = tid & 15;
                const float4 e = __ldg(&reinterpret_cast<const float4*>(tok_emb)[row * (H / 4) + kc * KC4 + k4]);
                sET[(k4 * 4 + 0) * 8 + row] = e.x;
                sET[(k4 * 4 + 1) * 8 + row] = e.y;
                sET[(k4 * 4 + 2) * 8 + row] = e.z;
                sET[(k4 * 4 + 3) * 8 + row] = e.w;
            }
            __syncthreads();

            float acc[8];
            #pragma unroll
            for (int r = 0; r < 8; r++) acc[r] = 0.f;
            #pragma unroll
            for (int kk = 0; kk < 8; kk++) {
                const int k = kq * 8 + kk;
                const float wv = sW[k * SWP + ch];
                const float4 e0 = *reinterpret_cast<const float4*>(&sET[k * 8]);
                const float4 e1 = *reinterpret_cast<const float4*>(&sET[k * 8 + 4]);
                acc[0] += wv * e0.x; acc[1] += wv * e0.y; acc[2] += wv * e0.z; acc[3] += wv * e0.w;
                acc[4] += wv * e1.x; acc[5] += wv * e1.y; acc[6] += wv * e1.z; acc[7] += wv * e1.w;
            }
            #pragma unroll
            for (int r = 0; r < 8; r++) sAcc[kq * 256 + r * 32 + ch] = acc[r];
            __syncthreads();

            float v = 0.f;
            #pragma unroll
            for (int q = 0; q < 8; q++) v += sAcc[q * 256 + tid];
            g_ptok[(kc * 8 + (tid >> 5)) * H + ct * 32 + (tid & 31)] = v;
        } else {
            const int b2 = bid - NB_TOK;
            const int kc = b2 / NCT;
            const int ct = b2 % NCT;

            float* sW   = smem_buf;
            float* sET  = smem_buf + 2112;
            float* sAcc = smem_buf + 2112 + 1024;

            #pragma unroll
            for (int t = 0; t < 2; t++) {
                const int idx = t * 256 + tid;
                const int c   = idx / KC4;
                const int k4  = idx % KC4;
                const float4 w = __ldg(&W4[(size_t)(ct * 32 + c) * (WIN / 4) + (H / 4) + kc * KC4 + k4]);
                float* dst = &sW[(k4 * 4) * SWP + c];
                dst[0 * SWP] = w.x; dst[1 * SWP] = w.y; dst[2 * SWP] = w.z; dst[3 * SWP] = w.w;
            }
            {
                const int row = tid >> 4;
                const int k4  = tid & 15;
                const float4 e = __ldg(&reinterpret_cast<const float4*>(din_emb)[row * (DD / 4) + kc * KC4 + k4]);
                sET[(k4 * 4 + 0) * 16 + row] = e.x;
                sET[(k4 * 4 + 1) * 16 + row] = e.y;
                sET[(k4 * 4 + 2) * 16 + row] = e.z;
                sET[(k4 * 4 + 3) * 16 + row] = e.w;
            }
            __syncthreads();

            float acc[16];
            #pragma unroll
            for (int r = 0; r < 16; r++) acc[r] = 0.f;
            #pragma unroll
            for (int kk = 0; kk < 8; kk++) {
                const int k = kq * 8 + kk;
                const float wv = sW[k * SWP + ch];
                #pragma unroll
                for (int p = 0; p < 4; p++) {
                    const float4 e = *reinterpret_cast<const float4*>(&sET[k * 16 + p * 4]);
                    acc[p * 4 + 0] += wv * e.x; acc[p * 4 + 1] += wv * e.y;
                    acc[p * 4 + 2] += wv * e.z; acc[p * 4 + 3] += wv * e.w;
                }
            }
            #pragma unroll
            for (int r = 0; r < 16; r++) sAcc[kq * 512 + r * 32 + ch] = acc[r];
            __syncthreads();

            #pragma unroll
            for (int h = 0; h < 2; h++) {
                const int o = h * 256 + tid;
                float v = 0.f;
                #pragma unroll
                for (int q = 0; q < 8; q++) v += sAcc[q * 512 + o];
                g_pdin[(kc * 16 + (o >> 5)) * H + ct * 32 + (o & 31)] = v;
            }
        }
        __threadfence();
        __syncthreads();
        if (tid == 0) atomicAdd(&g_cnt_partial, 1);

    } else if (bid < NB_P + NB_COMBO) {
        // ==================== combo precompute ====================
        __shared__ int s_is64;
        if (tid == 0) {
            int ok = 1;
            #pragma unroll 8
            for (int i = 0; i < 64; i++)
                if (ids32[2 * i + 1] != 0) ok = 0;
            s_is64 = ok;
        }
        __syncthreads();
        const int stride = s_is64 ? 2 : 1;

        const int cb   = bid - NB_P;
        const int base = cb * 1024 + tid * 4;
        unsigned char cc[4];
        #pragma unroll
        for (int j = 0; j < 4; j++) {
            const int t = base + j;
            int combo = 0;
            if (t < n_tokens) {
                const int a = __ldg(&ids32[t * stride]);
                const int s = t & (SEQ - 1);
                if (s == SEQ - 1) {
                    combo = a * 17 + 16;
                } else {
                    const int nx = __ldg(&ids32[(t + 1) * stride]);
                    const int dd = (a >= 4 && nx >= 4) ? ((a - 4) * 4 + (nx - 4)) : 0;
                    combo = a * 17 + dd;
                }
            }
            cc[j] = (unsigned char)combo;
        }
        uchar4 c4; c4.x = cc[0]; c4.y = cc[1]; c4.z = cc[2]; c4.w = cc[3];
        reinterpret_cast<uchar4*>(g_combo4)[cb * 256 + tid] = c4;

        __threadfence();
        __syncthreads();
        if (tid == 0) atomicAdd(&g_cnt_combo, 1);

    } else if (bid < NB_WORK) {
        // ==================== table rows ====================
        const int combo = bid - (NB_P + NB_COMBO);
        const int a = combo / 17;
        const int d = combo % 17;
        const int lane = tid & 31;
        const int warp = tid >> 5;

        if (tid == 0) {
            const int my     = atomicAdd(&g_started, 1);
            const int epoch  = my / (NCOMBO + nb_gather);
            const int target = (epoch + 1) * NB_P;
            while (__ldcg(&g_cnt_partial) < target) __nanosleep(64);
        }
        __syncthreads();
        __threadfence();

        float x[3];
        #pragma unroll
        for (int j = 0; j < 3; j++) {
            const int o = j * 256 + tid;
            float v = bias[o];
            #pragma unroll
            for (int kc = 0; kc < NK_TOK; kc++) v += g_ptok[(kc * 8 + a) * H + o];
            if (d < 16) {
                #pragma unroll
                for (int kc = 0; kc < NK_DIN; kc++) v += g_pdin[(kc * 16 + d) * H + o];
            }
            x[j] = v;
        }

        float* sred = smem_buf;
        float* sbc  = smem_buf + 8;

        float s = x[0] + x[1] + x[2];
        #pragma unroll
        for (int off = 16; off > 0; off >>= 1) s += __shfl_down_sync(0xffffffffu, s, off);
        if (lane == 0) sred[warp] = s;
        __syncthreads();
        if (tid == 0) {
            float t = 0.f;
            #pragma unroll
            for (int w = 0; w < 8; w++) t += sred[w];
            sbc[0] = t * (1.0f / H);
        }
        __syncthreads();
        const float mu = sbc[0];

        float dx[3];
        #pragma unroll
        for (int j = 0; j < 3; j++) dx[j] = x[j] - mu;
        float s2 = dx[0] * dx[0] + dx[1] * dx[1] + dx[2] * dx[2];
        #pragma unroll
        for (int off = 16; off > 0; off >>= 1) s2 += __shfl_down_sync(0xffffffffu, s2, off);
        if (lane == 0) sred[warp] = s2;
        __syncthreads();
        if (tid == 0) {
            float t = 0.f;
            #pragma unroll
            for (int w = 0; w < 8; w++) t += sred[w];
            sbc[1] = t * (1.0f / H);
        }
        __syncthreads();
        const float inv = rsqrtf(sbc[1] + LN_EPS);

        #pragma unroll
        for (int j = 0; j < 3; j++) {
            const int o = j * 256 + tid;
            g_table[combo * H + o] = dx[j] * inv * gamma[o] + beta[o];
        }

        __threadfence();
        __syncthreads();
        if (tid == 0) atomicAdd(&g_cnt_table, 1);

    } else {
        // ==================== gather ====================
        const int gb = bid - NB_WORK;

        if (tid == 0) {
            const int my    = atomicAdd(&g_started, 1);
            const int epoch = my / (NCOMBO + nb_gather);
            const int tt    = (epoch + 1) * NCOMBO;
            const int tc    = (epoch + 1) * NB_COMBO;
            while (__ldcg(&g_cnt_table)  < tt) __nanosleep(128);
            while (__ldcg(&g_cnt_combo) < tc) __nanosleep(64);
        }
        __syncthreads();
        __threadfence();

        if (tid < 192) {
            const uint4 c16 = __ldg(&g_combo4[gb]);
            unsigned char cc[16];
            *reinterpret_cast<uint4*>(cc) = c16;

            const float4* tab4 = reinterpret_cast<const float4*>(g_table);
            float4* out4 = reinterpret_cast<float4*>(out)
                         + (size_t)gb * TOK_PER_BLK * (H / 4) + tid;

            // depth-8 prefetch ring (fully unrolled, compile-time indexing)
            float4 b[8];
            #pragma unroll
            for (int i = 0; i < 8; i++)
                b[i] = __ldg(&tab4[(int)cc[i] * (H / 4) + tid]);

            #pragma unroll
            for (int i = 0; i < 8; i++) {
                const float4 v = b[i];
                b[i] = __ldg(&tab4[(int)cc[i + 8] * (H / 4) + tid]);
                __stcs(&out4[(size_t)i * (H / 4)], v);
            }
            #pragma unroll
            for (int i = 0; i < 8; i++)
                __stcs(&out4[(size_t)(i + 8) * (H / 4)], b[i]);
        }
    }
}

// ---------------------------------------------------------------------------
extern "C" void kernel_launch(void* const* d_in, const int* in_sizes, int n_in,
                              void* d_out, int out_size) {
    const int*   ids32   = (const int*)d_in[0];
    const float* tok_emb = (const float*)d_in[1];
    const float* din_emb = (const float*)d_in[2];
    const float* W       = (const float*)d_in[3];
    const float* bias    = (const float*)d_in[4];
    const float* gamma   = (const float*)d_in[5];
    const float* beta    = (const float*)d_in[6];
    float*       out     = (float*)d_out;

    const int n_tokens  = in_sizes[0];                           // 65536
    const int nb_gather = (n_tokens + TOK_PER_BLK - 1) / TOK_PER_BLK;

    mega_kernel<<<NB_WORK + nb_gather, 256>>>(
        ids32, tok_emb, din_emb, W, bias, gamma, beta, out,
        n_tokens, nb_gather);
}

// round 17
// speedup vs baseline: 1.1175x; 1.1175x over previous
#include <cuda_runtime.h>

#define H      768
#define DD     192
#define WIN    960
#define NCOMBO (8 * 17)
#define SEQ    2048
#define LN_EPS 1e-12f
#define TOK_PER_BLK 16

#define KC      64
#define KC4     16
#define NK_TOK  12          // 768/64
#define NK_DIN  3           // 192/64
#define NCT     24
#define SWP     33

#define NB_TOK   (NK_TOK * NCT)          // 288
#define NB_DIN   (NK_DIN * NCT)          // 72
#define NB_P     (NB_TOK + NB_DIN)       // 360 GEMM blocks
#define NB_COMBO 64
#define NB_WORK  (NB_P + NB_COMBO + NCOMBO)   // 560

// Scratch (no cudaMalloc allowed). Counter is zero at module load; the
// gather kernel resets it AFTER cudaGridDependencySynchronize(), i.e.
// strictly after the whole preamble grid has completed.
__device__ float g_ptok[NK_TOK * 8 * H];
__device__ float g_pdin[NK_DIN * 16 * H];
__device__ float g_table[NCOMBO * H];
__device__ uint4 g_combo4[4096];
__device__ int   g_cnt_partial;

// ---------------------------------------------------------------------------
// Kernel A: fused preamble (R15-identical math). 560 blocks x 256 threads,
// 29 KB smem (7 blocks/SM -> all 560 resident wave 1 -> spin deadlock-free).
// Each block fires the PDL trigger at its end so the gather grid can begin
// its launch/scheduling ramp while the preamble tail drains.
// ---------------------------------------------------------------------------
__global__ __launch_bounds__(256) void preamble_kernel(
    const int*   __restrict__ ids32,
    const float* __restrict__ tok_emb,   // [8, 768]
    const float* __restrict__ din_emb,   // [16, 192]
    const float* __restrict__ W,         // [768, 960]
    const float* __restrict__ bias,
    const float* __restrict__ gamma,
    const float* __restrict__ beta,
    int n_tokens)
{
    __shared__ float smem_buf[7232];     // 28.9 KB
    const int tid = threadIdx.x;
    const int bid = blockIdx.x;

    if (bid < NB_P) {
        // ==================== GEMM partials ====================
        const int ch = tid & 31;
        const int kq = tid >> 5;
        const float4* W4 = reinterpret_cast<const float4*>(W);

        if (bid < NB_TOK) {
            const int kc = bid / NCT;
            const int ct = bid % NCT;

            float* sW   = smem_buf;
            float* sET  = smem_buf + 2112;
            float* sAcc = smem_buf + 2112 + 512;

            #pragma unroll
            for (int t = 0; t < 2; t++) {
                const int idx = t * 256 + tid;
                const int c   = idx / KC4;
                const int k4  = idx % KC4;
                const float4 w = __ldg(&W4[(size_t)(ct * 32 + c) * (WIN / 4) + kc * KC4 + k4]);
                float* dst = &sW[(k4 * 4) * SWP + c];
                dst[0 * SWP] = w.x; dst[1 * SWP] = w.y; dst[2 * SWP] = w.z; dst[3 * SWP] = w.w;
            }
            if (tid < 128) {
                const int row = tid >> 4;
                const int k4  = tid & 15;
                const float4 e = __ldg(&reinterpret_cast<const float4*>(tok_emb)[row * (H / 4) + kc * KC4 + k4]);
                sET[(k4 * 4 + 0) * 8 + row] = e.x;
                sET[(k4 * 4 + 1) * 8 + row] = e.y;
                sET[(k4 * 4 + 2) * 8 + row] = e.z;
                sET[(k4 * 4 + 3) * 8 + row] = e.w;
            }
            __syncthreads();

            float acc[8];
            #pragma unroll
            for (int r = 0; r < 8; r++) acc[r] = 0.f;
            #pragma unroll
            for (int kk = 0; kk < 8; kk++) {
                const int k = kq * 8 + kk;
                const float wv = sW[k * SWP + ch];
                const float4 e0 = *reinterpret_cast<const float4*>(&sET[k * 8]);
                const float4 e1 = *reinterpret_cast<const float4*>(&sET[k * 8 + 4]);
                acc[0] += wv * e0.x; acc[1] += wv * e0.y; acc[2] += wv * e0.z; acc[3] += wv * e0.w;
                acc[4] += wv * e1.x; acc[5] += wv * e1.y; acc[6] += wv * e1.z; acc[7] += wv * e1.w;
            }
            #pragma unroll
            for (int r = 0; r < 8; r++) sAcc[kq * 256 + r * 32 + ch] = acc[r];
            __syncthreads();

            float v = 0.f;
            #pragma unroll
            for (int q = 0; q < 8; q++) v += sAcc[q * 256 + tid];
            g_ptok[(kc * 8 + (tid >> 5)) * H + ct * 32 + (tid & 31)] = v;
        } else {
            const int b2 = bid - NB_TOK;
            const int kc = b2 / NCT;
            const int ct = b2 % NCT;

            float* sW   = smem_buf;
            float* sET  = smem_buf + 2112;
            float* sAcc = smem_buf + 2112 + 1024;

            #pragma unroll
            for (int t = 0; t < 2; t++) {
                const int idx = t * 256 + tid;
                const int c   = idx / KC4;
                const int k4  = idx % KC4;
                const float4 w = __ldg(&W4[(size_t)(ct * 32 + c) * (WIN / 4) + (H / 4) + kc * KC4 + k4]);
                float* dst = &sW[(k4 * 4) * SWP + c];
                dst[0 * SWP] = w.x; dst[1 * SWP] = w.y; dst[2 * SWP] = w.z; dst[3 * SWP] = w.w;
            }
            {
                const int row = tid >> 4;
                const int k4  = tid & 15;
                const float4 e = __ldg(&reinterpret_cast<const float4*>(din_emb)[row * (DD / 4) + kc * KC4 + k4]);
                sET[(k4 * 4 + 0) * 16 + row] = e.x;
                sET[(k4 * 4 + 1) * 16 + row] = e.y;
                sET[(k4 * 4 + 2) * 16 + row] = e.z;
                sET[(k4 * 4 + 3) * 16 + row] = e.w;
            }
            __syncthreads();

            float acc[16];
            #pragma unroll
            for (int r = 0; r < 16; r++) acc[r] = 0.f;
            #pragma unroll
            for (int kk = 0; kk < 8; kk++) {
                const int k = kq * 8 + kk;
                const float wv = sW[k * SWP + ch];
                #pragma unroll
                for (int p = 0; p < 4; p++) {
                    const float4 e = *reinterpret_cast<const float4*>(&sET[k * 16 + p * 4]);
                    acc[p * 4 + 0] += wv * e.x; acc[p * 4 + 1] += wv * e.y;
                    acc[p * 4 + 2] += wv * e.z; acc[p * 4 + 3] += wv * e.w;
                }
            }
            #pragma unroll
            for (int r = 0; r < 16; r++) sAcc[kq * 512 + r * 32 + ch] = acc[r];
            __syncthreads();

            #pragma unroll
            for (int h = 0; h < 2; h++) {
                const int o = h * 256 + tid;
                float v = 0.f;
                #pragma unroll
                for (int q = 0; q < 8; q++) v += sAcc[q * 512 + o];
                g_pdin[(kc * 16 + (o >> 5)) * H + ct * 32 + (o & 31)] = v;
            }
        }
        __threadfence();
        __syncthreads();
        if (tid == 0) atomicAdd(&g_cnt_partial, 1);

    } else if (bid < NB_P + NB_COMBO) {
        // ==================== combo precompute ====================
        __shared__ int s_is64;
        if (tid == 0) {
            int ok = 1;
            #pragma unroll 8
            for (int i = 0; i < 64; i++)
                if (ids32[2 * i + 1] != 0) ok = 0;
            s_is64 = ok;
        }
        __syncthreads();
        const int stride = s_is64 ? 2 : 1;

        const int cb   = bid - NB_P;
        const int base = cb * 1024 + tid * 4;
        unsigned char cc[4];
        #pragma unroll
        for (int j = 0; j < 4; j++) {
            const int t = base + j;
            int combo = 0;
            if (t < n_tokens) {
                const int a = __ldg(&ids32[t * stride]);
                const int s = t & (SEQ - 1);
                if (s == SEQ - 1) {
                    combo = a * 17 + 16;
                } else {
                    const int nx = __ldg(&ids32[(t + 1) * stride]);
                    const int dd = (a >= 4 && nx >= 4) ? ((a - 4) * 4 + (nx - 4)) : 0;
                    combo = a * 17 + dd;
                }
            }
            cc[j] = (unsigned char)combo;
        }
        uchar4 c4; c4.x = cc[0]; c4.y = cc[1]; c4.z = cc[2]; c4.w = cc[3];
        reinterpret_cast<uchar4*>(g_combo4)[cb * 256 + tid] = c4;

    } else {
        // ==================== table rows ====================
        const int combo = bid - (NB_P + NB_COMBO);
        const int a = combo / 17;
        const int d = combo % 17;
        const int lane = tid & 31;
        const int warp = tid >> 5;

        if (tid == 0) {
            while (__ldcg(&g_cnt_partial) < NB_P) __nanosleep(64);
        }
        __syncthreads();
        __threadfence();

        float x[3];
        #pragma unroll
        for (int j = 0; j < 3; j++) {
            const int o = j * 256 + tid;
            float v = bias[o];
            #pragma unroll
            for (int kc = 0; kc < NK_TOK; kc++) v += g_ptok[(kc * 8 + a) * H + o];
            if (d < 16) {
                #pragma unroll
                for (int kc = 0; kc < NK_DIN; kc++) v += g_pdin[(kc * 16 + d) * H + o];
            }
            x[j] = v;
        }

        float* sred = smem_buf;
        float* sbc  = smem_buf + 8;

        float s = x[0] + x[1] + x[2];
        #pragma unroll
        for (int off = 16; off > 0; off >>= 1) s += __shfl_down_sync(0xffffffffu, s, off);
        if (lane == 0) sred[warp] = s;
        __syncthreads();
        if (tid == 0) {
            float t = 0.f;
            #pragma unroll
            for (int w = 0; w < 8; w++) t += sred[w];
            sbc[0] = t * (1.0f / H);
        }
        __syncthreads();
        const float mu = sbc[0];

        float dx[3];
        #pragma unroll
        for (int j = 0; j < 3; j++) dx[j] = x[j] - mu;
        float s2 = dx[0] * dx[0] + dx[1] * dx[1] + dx[2] * dx[2];
        #pragma unroll
        for (int off = 16; off > 0; off >>= 1) s2 += __shfl_down_sync(0xffffffffu, s2, off);
        if (lane == 0) sred[warp] = s2;
        __syncthreads();
        if (tid == 0) {
            float t = 0.f;
            #pragma unroll
            for (int w = 0; w < 8; w++) t += sred[w];
            sbc[1] = t * (1.0f / H);
        }
        __syncthreads();
        const float inv = rsqrtf(sbc[1] + LN_EPS);

        #pragma unroll
        for (int j = 0; j < 3; j++) {
            const int o = j * 256 + tid;
            g_table[combo * H + o] = dx[j] * inv * gamma[o] + beta[o];
        }
    }

    // PDL: allow the gather grid to begin its launch ramp now.
    cudaTriggerProgrammaticLaunchCompletion();
}

// ---------------------------------------------------------------------------
// Kernel B: gather, R15-identical ring. __launch_bounds__(192,5) keeps the
// depth-8 prefetch real (regs ~62). cudaGridDependencySynchronize() orders
// all table/combo reads after the full preamble grid; the counter reset
// after it is therefore safe.
// ---------------------------------------------------------------------------
__global__ __launch_bounds__(192, 5) void gather_kernel(
    float* __restrict__ out)
{
    cudaGridDependencySynchronize();

    if (blockIdx.x == 0 && threadIdx.x == 0) g_cnt_partial = 0;

    const int tid = threadIdx.x;
    const uint4 c16 = __ldg(&g_combo4[blockIdx.x]);

    unsigned char cc[16];
    *reinterpret_cast<uint4*>(cc) = c16;

    const float4* tab4 = reinterpret_cast<const float4*>(g_table);
    float4* out4 = reinterpret_cast<float4*>(out)
                 + (size_t)blockIdx.x * TOK_PER_BLK * (H / 4) + tid;

    // Fill the 8-deep ring: 8 independent LDG.128 issued back-to-back.
    float4 b[8];
    #pragma unroll
    for (int i = 0; i < 8; i++)
        b[i] = __ldg(&tab4[(int)cc[i] * (H / 4) + tid]);

    // Steady state: refill slot i with row i+8 before storing row i.
    #pragma unroll
    for (int i = 0; i < 8; i++) {
        const float4 v = b[i];
        b[i] = __ldg(&tab4[(int)cc[i + 8] * (H / 4) + tid]);
        __stcs(&out4[(size_t)i * (H / 4)], v);
    }
    // Drain the ring.
    #pragma unroll
    for (int i = 0; i < 8; i++)
        __stcs(&out4[(size_t)(i + 8) * (H / 4)], b[i]);
}

// ---------------------------------------------------------------------------
extern "C" void kernel_launch(void* const* d_in, const int* in_sizes, int n_in,
                              void* d_out, int out_size) {
    const int*   ids32   = (const int*)d_in[0];
    const float* tok_emb = (const float*)d_in[1];
    const float* din_emb = (const float*)d_in[2];
    const float* W       = (const float*)d_in[3];
    const float* bias    = (const float*)d_in[4];
    const float* gamma   = (const float*)d_in[5];
    const float* beta    = (const float*)d_in[6];
    float*       out     = (float*)d_out;

    const int n_tokens  = in_sizes[0];                           // 65536
    const int nb_gather = (n_tokens + TOK_PER_BLK - 1) / TOK_PER_BLK;

    preamble_kernel<<<NB_WORK, 256>>>(ids32, tok_emb, din_emb, W,
                                      bias, gamma, beta, n_tokens);

    // PDL launch: gather's ramp overlaps the preamble tail; data ordering
    // comes from cudaGridDependencySynchronize() inside the kernel.
    cudaLaunchConfig_t cfg = {};
    cfg.gridDim  = dim3((unsigned)nb_gather, 1, 1);
    cfg.blockDim = dim3(192, 1, 1);
    cfg.dynamicSmemBytes = 0;
    cfg.stream = 0;
    cudaLaunchAttribute attrs[1];
    attrs[0].id = cudaLaunchAttributeProgrammaticStreamSerialization;
    attrs[0].val.programmaticStreamSerializationAllowed = 1;
    cfg.attrs = attrs;
    cfg.numAttrs = 1;
    cudaLaunchKernelEx(&cfg, gather_kernel, out);
}